// round 12
// baseline (speedup 1.0000x reference)
#include <cuda_runtime.h>
#include <cuda_fp16.h>
#include <cstdint>

#define N_NODES 2048
#define F_DIM   128
#define UNITS   128
#define FE_DIM  16
#define DEG     64
#define N_EDGES (N_NODES * DEG)

__device__ __half g_hr[N_NODES * UNITS];   // fp16 hr
__device__ float  g_al[N_NODES];
__device__ float  g_ar[N_NODES];
__device__ float  g_dot[N_EDGES];          // ef[src,dst] . wev

__device__ __forceinline__ float lrelu(float x) {
    return x > 0.0f ? x : 0.2f * x;
}

__device__ __forceinline__ unsigned long long pack2(float lo, float hi) {
    unsigned long long r;
    asm("mov.b64 %0, {%1, %2};" : "=l"(r) : "f"(lo), "f"(hi));
    return r;
}
__device__ __forceinline__ void unpack2(float& lo, float& hi, unsigned long long v) {
    asm("mov.b64 {%0, %1}, %2;" : "=f"(lo), "=f"(hi) : "l"(v));
}
__device__ __forceinline__ void fma2(unsigned long long& d,
                                     unsigned long long a,
                                     unsigned long long b) {
    asm("fma.rn.f32x2 %0, %1, %2, %3;" : "=l"(d) : "l"(a), "l"(b), "l"(d));
}

// ---- Kernel G: side-split GEMM (exact R8 body, proven 6.3us) ----
#define NPB   8
#define NSPAD 12
__global__ __launch_bounds__(128)
void gemm_kernel(const float* __restrict__ ns,
                 const float* __restrict__ Wl,
                 const float* __restrict__ Wr,
                 const float* __restrict__ W_attn) {
    const int b    = blockIdx.x;
    const int side = b >> 8;               // 0 = L, 1 = R
    const int t    = threadIdx.x;
    const int n0   = (b & 255) * NPB;

    __shared__ float s_ns[F_DIM][NSPAD];
    #pragma unroll
    for (int j = 0; j < NPB; j++)
        s_ns[t][j] = ns[(n0 + j) * F_DIM + t];
    __syncthreads();

    const float* __restrict__ W = side ? Wr : Wl;

    unsigned long long acc[4];
    #pragma unroll
    for (int j = 0; j < 4; j++) acc[j] = 0ull;

    #pragma unroll 8
    for (int k = 0; k < F_DIM; k++) {
        const float wv = W[k * UNITS + t];
        const unsigned long long wp = pack2(wv, wv);
        const ulonglong2* row = reinterpret_cast<const ulonglong2*>(&s_ns[k][0]);
        const ulonglong2 r0 = row[0];
        const ulonglong2 r1 = row[1];
        fma2(acc[0], r0.x, wp);
        fma2(acc[1], r0.y, wp);
        fma2(acc[2], r1.x, wp);
        fma2(acc[3], r1.y, wp);
    }

    float h[NPB];
    #pragma unroll
    for (int j = 0; j < 4; j++) unpack2(h[2 * j], h[2 * j + 1], acc[j]);

    if (side) {
        #pragma unroll
        for (int j = 0; j < NPB; j++)
            g_hr[(n0 + j) * UNITS + t] = __float2half_rn(h[j]);
    }

    const float wa = W_attn[side * UNITS + t];
    __shared__ float s_red[NPB][4];
    const int w = t >> 5, lane = t & 31;

    #pragma unroll
    for (int j = 0; j < NPB; j++) {
        float p = lrelu(h[j]) * wa;
        #pragma unroll
        for (int o = 16; o > 0; o >>= 1)
            p += __shfl_down_sync(0xffffffffu, p, o);
        if (lane == 0) s_red[j][w] = p;
    }
    __syncthreads();
    if (t < NPB) {
        float* dstv = side ? g_ar : g_al;
        dstv[n0 + t] = s_red[t][0] + s_red[t][1] + s_red[t][2] + s_red[t][3];
    }
}

// ---- Kernel D: ef gather + dot (runs CONCURRENTLY with gemm) ----
__global__ __launch_bounds__(256)
void dot_kernel(const int* __restrict__ edges,
                const float* __restrict__ ef,
                const float* __restrict__ W_edge,
                const float* __restrict__ W_attn) {
    const int t = threadIdx.x;

    __shared__ float s_wev[FE_DIM];
    if (t < FE_DIM) {
        float s = 0.0f;
        #pragma unroll
        for (int j = 0; j < FE_DIM; j++)
            s += W_edge[t * FE_DIM + j] * W_attn[2 * UNITS + j];
        s_wev[t] = s;
    }
    __syncthreads();

    const int e   = blockIdx.x * 256 + t;
    const int src = e >> 6;                          // src == repeat(arange)
    const int dst = edges[2 * e + 1];
    const float4* p = reinterpret_cast<const float4*>(
        ef + ((size_t)src * N_NODES + (size_t)dst) * FE_DIM);
    float dot = 0.0f;
    #pragma unroll
    for (int i = 0; i < 4; i++) {
        const float4 v = p[i];
        dot = fmaf(v.x, s_wev[4 * i + 0], dot);
        dot = fmaf(v.y, s_wev[4 * i + 1], dot);
        dot = fmaf(v.z, s_wev[4 * i + 2], dot);
        dot = fmaf(v.w, s_wev[4 * i + 3], dot);
    }
    g_dot[e] = dot;
}

// ---- Kernel B: attn (exact R10 body, proven 8.0us) ----
__global__ __launch_bounds__(128)
void attn_kernel(const int* __restrict__ edges,
                 float* __restrict__ out) {
    const int n = blockIdx.x;
    const int t = threadIdx.x;
    const int w = t >> 5, lane = t & 31;

    __shared__ float s_score[DEG];
    __shared__ int   s_dst[DEG];
    __shared__ float s_acc[4][UNITS];
    __shared__ float s_part[2];
    __shared__ float s_inv;

    if (t < DEG) {
        const int e   = n * DEG + t;
        const int dst = edges[2 * e + 1];
        float s = g_al[n] + g_ar[dst] + g_dot[e];
        s = fminf(2.0f, fmaxf(-2.0f, s));
        const float sc = __expf(s);
        s_score[t] = sc;
        s_dst[t]   = dst;

        float v = sc;
        #pragma unroll
        for (int o = 16; o > 0; o >>= 1)
            v += __shfl_down_sync(0xffffffffu, v, o);
        if (lane == 0) s_part[t >> 5] = v;
    }
    __syncthreads();
    if (t == 0) s_inv = 1.0f / (s_part[0] + s_part[1]);

    const int ebase = w * 16;
    const int sub   = lane >> 4;
    const int c0    = (lane & 15) * 8;

    float acc[8];
    #pragma unroll
    for (int k = 0; k < 8; k++) acc[k] = 0.0f;

    #pragma unroll
    for (int i = 0; i < 8; i++) {
        const int e = ebase + 2 * i + sub;
        const float sc = s_score[e];
        const int4 hv = *reinterpret_cast<const int4*>(
            g_hr + s_dst[e] * UNITS + c0);
        const __half2* hp = reinterpret_cast<const __half2*>(&hv);
        #pragma unroll
        for (int k = 0; k < 4; k++) {
            const float2 f = __half22float2(hp[k]);
            acc[2 * k]     = fmaf(sc, f.x, acc[2 * k]);
            acc[2 * k + 1] = fmaf(sc, f.y, acc[2 * k + 1]);
        }
    }
    #pragma unroll
    for (int k = 0; k < 8; k++)
        acc[k] += __shfl_down_sync(0xffffffffu, acc[k], 16);

    if (lane < 16) {
        *reinterpret_cast<float4*>(&s_acc[w][c0]) =
            make_float4(acc[0], acc[1], acc[2], acc[3]);
        *reinterpret_cast<float4*>(&s_acc[w][c0 + 4]) =
            make_float4(acc[4], acc[5], acc[6], acc[7]);
    }
    __syncthreads();

    out[n * UNITS + t] =
        (s_acc[0][t] + s_acc[1][t] + s_acc[2][t] + s_acc[3][t]) * s_inv;
}

extern "C" void kernel_launch(void* const* d_in, const int* in_sizes, int n_in,
                              void* d_out, int out_size) {
    const float* ns      = (const float*)d_in[0];
    const int*   edges   = (const int*)d_in[1];
    const float* ef      = (const float*)d_in[2];
    const float* W_left  = (const float*)d_in[3];
    const float* W_right = (const float*)d_in[4];
    const float* W_attn  = (const float*)d_in[5];
    const float* W_edge  = (const float*)d_in[6];
    float* out = (float*)d_out;

    // Capture-fork: dot (DRAM-bound) runs concurrently with gemm (L1/FMA-bound)
    // as a parallel graph branch. Stream/events are host objects (no device
    // memory); created per call and intentionally not destroyed so the capture
    // state never references a destroyed object. Our plain <<<>>> launches are
    // captured, so stream handle 0 as seen from this TU is the capturing stream.
    cudaStream_t s2;
    cudaEvent_t e_fork, e_join;
    cudaStreamCreateWithFlags(&s2, cudaStreamNonBlocking);
    cudaEventCreateWithFlags(&e_fork, cudaEventDisableTiming);
    cudaEventCreateWithFlags(&e_join, cudaEventDisableTiming);

    cudaEventRecord(e_fork, 0);
    cudaStreamWaitEvent(s2, e_fork, 0);

    dot_kernel<<<N_EDGES / 256, 256, 0, s2>>>(edges, ef, W_edge, W_attn);
    gemm_kernel<<<512, 128>>>(ns, W_left, W_right, W_attn);

    cudaEventRecord(e_join, s2);
    cudaStreamWaitEvent(0, e_join, 0);

    attn_kernel<<<N_NODES, 128>>>(edges, out);
}

// round 13
// speedup vs baseline: 1.6426x; 1.6426x over previous
#include <cuda_runtime.h>
#include <cuda_fp16.h>
#include <cstdint>

#define N_NODES 2048
#define F_DIM   128
#define UNITS   128
#define FE_DIM  16
#define DEG     64

__device__ __half g_hr[N_NODES * UNITS];   // fp16 hr: halves aggregation traffic
__device__ float  g_al[N_NODES];
__device__ float  g_ar[N_NODES];

__device__ __forceinline__ float lrelu(float x) {
    return x > 0.0f ? x : 0.2f * x;
}

__device__ __forceinline__ unsigned long long pack2(float lo, float hi) {
    unsigned long long r;
    asm("mov.b64 %0, {%1, %2};" : "=l"(r) : "f"(lo), "f"(hi));
    return r;
}
__device__ __forceinline__ void unpack2(float& lo, float& hi, unsigned long long v) {
    asm("mov.b64 {%0, %1}, %2;" : "=f"(lo), "=f"(hi) : "l"(v));
}
__device__ __forceinline__ void fma2(unsigned long long& d,
                                     unsigned long long a,
                                     unsigned long long b) {
    asm("fma.rn.f32x2 %0, %1, %2, %3;" : "=l"(d) : "l"(a), "l"(b), "l"(d));
}

// Kernel 1: side-split GEMM, NPB=16: 256 blocks x 128 threads.
//   blocks [0,128):   hl = ns @ Wl -> al    blocks [128,256): hr -> g_hr, ar
// W L2 traffic: 256 x 64KB = 16MB (half of NPB=8). Standalone (no mixed dot
// blocks), so the smem broadcasts stay conflict-free.
#define NPB   16
#define NSPAD 20   // 80B rows: multiple of 16B for aligned ulonglong2 reads
__global__ __launch_bounds__(128)
void gemm_kernel(const float* __restrict__ ns,
                 const float* __restrict__ Wl,
                 const float* __restrict__ Wr,
                 const float* __restrict__ W_attn) {
    const int b    = blockIdx.x;
    const int side = b >> 7;               // 0 = L, 1 = R
    const int t    = threadIdx.x;          // output column
    const int n0   = (b & 127) * NPB;

    __shared__ float s_ns[F_DIM][NSPAD];   // [k][node]
    #pragma unroll
    for (int j = 0; j < NPB; j++)
        s_ns[t][j] = ns[(n0 + j) * F_DIM + t];
    __syncthreads();

    const float* __restrict__ W = side ? Wr : Wl;

    unsigned long long acc[8];             // acc[j] = (h_{2j}, h_{2j+1})
    #pragma unroll
    for (int j = 0; j < 8; j++) acc[j] = 0ull;

    #pragma unroll 4
    for (int k = 0; k < F_DIM; k++) {
        const float wv = W[k * UNITS + t];           // coalesced, L1-cached
        const unsigned long long wp = pack2(wv, wv);
        const ulonglong2* row = reinterpret_cast<const ulonglong2*>(&s_ns[k][0]);
        const ulonglong2 r0 = row[0];
        const ulonglong2 r1 = row[1];
        const ulonglong2 r2 = row[2];
        const ulonglong2 r3 = row[3];
        fma2(acc[0], r0.x, wp);  fma2(acc[1], r0.y, wp);
        fma2(acc[2], r1.x, wp);  fma2(acc[3], r1.y, wp);
        fma2(acc[4], r2.x, wp);  fma2(acc[5], r2.y, wp);
        fma2(acc[6], r3.x, wp);  fma2(acc[7], r3.y, wp);
    }

    float h[NPB];
    #pragma unroll
    for (int j = 0; j < 8; j++) unpack2(h[2 * j], h[2 * j + 1], acc[j]);

    if (side) {
        #pragma unroll
        for (int j = 0; j < NPB; j++)
            g_hr[(n0 + j) * UNITS + t] = __float2half_rn(h[j]);
    }

    const float wa = W_attn[side * UNITS + t];
    __shared__ float s_red[NPB][4];
    const int w = t >> 5, lane = t & 31;

    #pragma unroll
    for (int j = 0; j < NPB; j++) {
        float p = lrelu(h[j]) * wa;
        #pragma unroll
        for (int o = 16; o > 0; o >>= 1)
            p += __shfl_down_sync(0xffffffffu, p, o);
        if (lane == 0) s_red[j][w] = p;
    }
    __syncthreads();
    if (t < NPB) {
        float* dstv = side ? g_ar : g_al;
        dstv[n0 + t] = s_red[t][0] + s_red[t][1] + s_red[t][2] + s_red[t][3];
    }
}

// Kernel 2: 1 node/block, 128 threads (proven shape).
// Gather phase now uses ALL 128 threads: 2 threads per edge, 32B each
// (2x LDG.128); partial dots combined through smem.
__global__ __launch_bounds__(128)
void attn_kernel(const int* __restrict__ edges,
                 const float* __restrict__ ef,
                 const float* __restrict__ W_edge,
                 const float* __restrict__ W_attn,
                 float* __restrict__ out) {
    const int n = blockIdx.x;
    const int t = threadIdx.x;
    const int w = t >> 5, lane = t & 31;

    __shared__ float s_wev[FE_DIM];
    __shared__ float s_pd[2][DEG];     // partial dots
    __shared__ float s_score[DEG];
    __shared__ int   s_dst[DEG];
    __shared__ float s_acc[4][UNITS];
    __shared__ float s_part[2];
    __shared__ float s_inv;

    // wev + dst staging
    if (t < FE_DIM) {
        float s = 0.0f;
        #pragma unroll
        for (int j = 0; j < FE_DIM; j++)
            s += W_edge[t * FE_DIM + j] * W_attn[2 * UNITS + j];
        s_wev[t] = s;
    }
    if (t < DEG)
        s_dst[t] = reinterpret_cast<const int2*>(edges)[n * DEG + t].y;
    __syncthreads();

    // gather: all 128 threads; thread = (edge er, half hf); 32B per thread.
    {
        const int er = t & 63;
        const int hf = t >> 6;
        const int dst = s_dst[er];
        const float4* p = reinterpret_cast<const float4*>(
            ef + ((size_t)n * N_NODES + (size_t)dst) * FE_DIM) + hf * 2;
        const float4 v0 = p[0];
        const float4 v1 = p[1];
        const float* wv = &s_wev[hf * 8];
        float d = 0.0f;
        d = fmaf(v0.x, wv[0], d);
        d = fmaf(v0.y, wv[1], d);
        d = fmaf(v0.z, wv[2], d);
        d = fmaf(v0.w, wv[3], d);
        d = fmaf(v1.x, wv[4], d);
        d = fmaf(v1.y, wv[5], d);
        d = fmaf(v1.z, wv[6], d);
        d = fmaf(v1.w, wv[7], d);
        s_pd[hf][er] = d;
    }
    __syncthreads();

    // scores + softmax denominator (threads 0..63)
    if (t < DEG) {
        const int dst = s_dst[t];
        float s = g_al[n] + g_ar[dst] + s_pd[0][t] + s_pd[1][t];
        s = fminf(2.0f, fmaxf(-2.0f, s));
        const float sc = __expf(s);
        s_score[t] = sc;

        float v = sc;
        #pragma unroll
        for (int o = 16; o > 0; o >>= 1)
            v += __shfl_down_sync(0xffffffffu, v, o);
        if (lane == 0) s_part[t >> 5] = v;
    }
    __syncthreads();
    if (t == 0) s_inv = 1.0f / (s_part[0] + s_part[1]);

    // aggregation: warp w -> edges [w*16, +16). Half-warp per edge; lane
    // loads 8 halves (16B LDG.128) of the fp16 hr row; fp32 accumulators.
    const int ebase = w * 16;
    const int sub   = lane >> 4;
    const int c0    = (lane & 15) * 8;

    float acc[8];
    #pragma unroll
    for (int k = 0; k < 8; k++) acc[k] = 0.0f;

    #pragma unroll
    for (int i = 0; i < 8; i++) {
        const int e = ebase + 2 * i + sub;
        const float sc = s_score[e];
        const int4 hv = *reinterpret_cast<const int4*>(
            g_hr + s_dst[e] * UNITS + c0);
        const __half2* hp = reinterpret_cast<const __half2*>(&hv);
        #pragma unroll
        for (int k = 0; k < 4; k++) {
            const float2 f = __half22float2(hp[k]);
            acc[2 * k]     = fmaf(sc, f.x, acc[2 * k]);
            acc[2 * k + 1] = fmaf(sc, f.y, acc[2 * k + 1]);
        }
    }
    #pragma unroll
    for (int k = 0; k < 8; k++)
        acc[k] += __shfl_down_sync(0xffffffffu, acc[k], 16);

    if (lane < 16) {
        *reinterpret_cast<float4*>(&s_acc[w][c0]) =
            make_float4(acc[0], acc[1], acc[2], acc[3]);
        *reinterpret_cast<float4*>(&s_acc[w][c0 + 4]) =
            make_float4(acc[4], acc[5], acc[6], acc[7]);
    }
    __syncthreads();   // also publishes s_inv

    out[n * UNITS + t] =
        (s_acc[0][t] + s_acc[1][t] + s_acc[2][t] + s_acc[3][t]) * s_inv;
}

extern "C" void kernel_launch(void* const* d_in, const int* in_sizes, int n_in,
                              void* d_out, int out_size) {
    const float* ns      = (const float*)d_in[0];
    const int*   edges   = (const int*)d_in[1];
    const float* ef      = (const float*)d_in[2];
    const float* W_left  = (const float*)d_in[3];
    const float* W_right = (const float*)d_in[4];
    const float* W_attn  = (const float*)d_in[5];
    const float* W_edge  = (const float*)d_in[6];
    float* out = (float*)d_out;

    gemm_kernel<<<256, 128>>>(ns, W_left, W_right, W_attn);
    attn_kernel<<<N_NODES, 128>>>(edges, ef, W_edge, W_attn, out);
}

// round 14
// speedup vs baseline: 1.9561x; 1.1909x over previous
#include <cuda_runtime.h>
#include <cuda_fp16.h>
#include <cstdint>

#define N_NODES 2048
#define F_DIM   128
#define UNITS   128
#define FE_DIM  16
#define DEG     64

__device__ __half g_hr[N_NODES * UNITS];   // fp16 hr: halves aggregation traffic
__device__ float  g_al[N_NODES];
__device__ float  g_ar[N_NODES];

__device__ __forceinline__ float lrelu(float x) {
    return x > 0.0f ? x : 0.2f * x;
}

__device__ __forceinline__ unsigned long long pack2(float lo, float hi) {
    unsigned long long r;
    asm("mov.b64 %0, {%1, %2};" : "=l"(r) : "f"(lo), "f"(hi));
    return r;
}
__device__ __forceinline__ void unpack2(float& lo, float& hi, unsigned long long v) {
    asm("mov.b64 {%0, %1}, %2;" : "=f"(lo), "=f"(hi) : "l"(v));
}
__device__ __forceinline__ void fma2(unsigned long long& d,
                                     unsigned long long a,
                                     unsigned long long b) {
    asm("fma.rn.f32x2 %0, %1, %2, %3;" : "=l"(d) : "l"(a), "l"(b), "l"(d));
}

// Kernel 1: side-split GEMM — exact R8/R9 body (proven ~6.5us).
// 512 blocks x 128 threads; blocks [0,256): L -> al; [256,512): R -> hr, ar.
#define NPB   8
#define NSPAD 12
__global__ __launch_bounds__(128)
void gemm_kernel(const float* __restrict__ ns,
                 const float* __restrict__ Wl,
                 const float* __restrict__ Wr,
                 const float* __restrict__ W_attn) {
    const int b    = blockIdx.x;
    const int side = b >> 8;               // 0 = L, 1 = R
    const int t    = threadIdx.x;          // output column
    const int n0   = (b & 255) * NPB;

    __shared__ float s_ns[F_DIM][NSPAD];   // [k][node]
    #pragma unroll
    for (int j = 0; j < NPB; j++)
        s_ns[t][j] = ns[(n0 + j) * F_DIM + t];
    __syncthreads();

    const float* __restrict__ W = side ? Wr : Wl;

    unsigned long long acc[4];             // acc[j] = (h_{2j}, h_{2j+1})
    #pragma unroll
    for (int j = 0; j < 4; j++) acc[j] = 0ull;

    #pragma unroll 8
    for (int k = 0; k < F_DIM; k++) {
        const float wv = W[k * UNITS + t];           // coalesced, L1-cached
        const unsigned long long wp = pack2(wv, wv);
        const ulonglong2* row = reinterpret_cast<const ulonglong2*>(&s_ns[k][0]);
        const ulonglong2 r0 = row[0];
        const ulonglong2 r1 = row[1];
        fma2(acc[0], r0.x, wp);
        fma2(acc[1], r0.y, wp);
        fma2(acc[2], r1.x, wp);
        fma2(acc[3], r1.y, wp);
    }

    float h[NPB];
    #pragma unroll
    for (int j = 0; j < 4; j++) unpack2(h[2 * j], h[2 * j + 1], acc[j]);

    if (side) {
        #pragma unroll
        for (int j = 0; j < NPB; j++)
            g_hr[(n0 + j) * UNITS + t] = __float2half_rn(h[j]);
    }

    const float wa = W_attn[side * UNITS + t];
    __shared__ float s_red[NPB][4];
    const int w = t >> 5, lane = t & 31;

    #pragma unroll
    for (int j = 0; j < NPB; j++) {
        float p = lrelu(h[j]) * wa;
        #pragma unroll
        for (int o = 16; o > 0; o >>= 1)
            p += __shfl_down_sync(0xffffffffu, p, o);
        if (lane == 0) s_red[j][w] = p;
    }
    __syncthreads();
    if (t < NPB) {
        float* dstv = side ? g_ar : g_al;
        dstv[n0 + t] = s_red[t][0] + s_red[t][1] + s_red[t][2] + s_red[t][3];
    }
}

// Kernel 2: R13 attn (proven 10.88us): 1 node/block, 128 threads;
// all-thread gather (2 threads/edge, 32B each), fp16 hr aggregation.
__global__ __launch_bounds__(128)
void attn_kernel(const int* __restrict__ edges,
                 const float* __restrict__ ef,
                 const float* __restrict__ W_edge,
                 const float* __restrict__ W_attn,
                 float* __restrict__ out) {
    const int n = blockIdx.x;
    const int t = threadIdx.x;
    const int w = t >> 5, lane = t & 31;

    __shared__ float s_wev[FE_DIM];
    __shared__ float s_pd[2][DEG];     // partial dots
    __shared__ float s_score[DEG];
    __shared__ int   s_dst[DEG];
    __shared__ float s_acc[4][UNITS];
    __shared__ float s_part[2];
    __shared__ float s_inv;

    // wev + dst staging
    if (t < FE_DIM) {
        float s = 0.0f;
        #pragma unroll
        for (int j = 0; j < FE_DIM; j++)
            s += W_edge[t * FE_DIM + j] * W_attn[2 * UNITS + j];
        s_wev[t] = s;
    }
    if (t < DEG)
        s_dst[t] = reinterpret_cast<const int2*>(edges)[n * DEG + t].y;
    __syncthreads();

    // gather: all 128 threads; thread = (edge er, half hf); 32B per thread.
    {
        const int er = t & 63;
        const int hf = t >> 6;
        const int dst = s_dst[er];
        const float4* p = reinterpret_cast<const float4*>(
            ef + ((size_t)n * N_NODES + (size_t)dst) * FE_DIM) + hf * 2;
        const float4 v0 = p[0];
        const float4 v1 = p[1];
        const float* wv = &s_wev[hf * 8];
        float d = 0.0f;
        d = fmaf(v0.x, wv[0], d);
        d = fmaf(v0.y, wv[1], d);
        d = fmaf(v0.z, wv[2], d);
        d = fmaf(v0.w, wv[3], d);
        d = fmaf(v1.x, wv[4], d);
        d = fmaf(v1.y, wv[5], d);
        d = fmaf(v1.z, wv[6], d);
        d = fmaf(v1.w, wv[7], d);
        s_pd[hf][er] = d;
    }
    __syncthreads();

    // scores + softmax denominator (threads 0..63)
    if (t < DEG) {
        const int dst = s_dst[t];
        float s = g_al[n] + g_ar[dst] + s_pd[0][t] + s_pd[1][t];
        s = fminf(2.0f, fmaxf(-2.0f, s));
        const float sc = __expf(s);
        s_score[t] = sc;

        float v = sc;
        #pragma unroll
        for (int o = 16; o > 0; o >>= 1)
            v += __shfl_down_sync(0xffffffffu, v, o);
        if (lane == 0) s_part[t >> 5] = v;
    }
    __syncthreads();
    if (t == 0) s_inv = 1.0f / (s_part[0] + s_part[1]);

    // aggregation: warp w -> edges [w*16, +16). Half-warp per edge; lane
    // loads 8 halves (16B LDG.128) of the fp16 hr row; fp32 accumulators.
    const int ebase = w * 16;
    const int sub   = lane >> 4;
    const int c0    = (lane & 15) * 8;

    float acc[8];
    #pragma unroll
    for (int k = 0; k < 8; k++) acc[k] = 0.0f;

    #pragma unroll
    for (int i = 0; i < 8; i++) {
        const int e = ebase + 2 * i + sub;
        const float sc = s_score[e];
        const int4 hv = *reinterpret_cast<const int4*>(
            g_hr + s_dst[e] * UNITS + c0);
        const __half2* hp = reinterpret_cast<const __half2*>(&hv);
        #pragma unroll
        for (int k = 0; k < 4; k++) {
            const float2 f = __half22float2(hp[k]);
            acc[2 * k]     = fmaf(sc, f.x, acc[2 * k]);
            acc[2 * k + 1] = fmaf(sc, f.y, acc[2 * k + 1]);
        }
    }
    #pragma unroll
    for (int k = 0; k < 8; k++)
        acc[k] += __shfl_down_sync(0xffffffffu, acc[k], 16);

    if (lane < 16) {
        *reinterpret_cast<float4*>(&s_acc[w][c0]) =
            make_float4(acc[0], acc[1], acc[2], acc[3]);
        *reinterpret_cast<float4*>(&s_acc[w][c0 + 4]) =
            make_float4(acc[4], acc[5], acc[6], acc[7]);
    }
    __syncthreads();   // also publishes s_inv

    out[n * UNITS + t] =
        (s_acc[0][t] + s_acc[1][t] + s_acc[2][t] + s_acc[3][t]) * s_inv;
}

extern "C" void kernel_launch(void* const* d_in, const int* in_sizes, int n_in,
                              void* d_out, int out_size) {
    const float* ns      = (const float*)d_in[0];
    const int*   edges   = (const int*)d_in[1];
    const float* ef      = (const float*)d_in[2];
    const float* W_left  = (const float*)d_in[3];
    const float* W_right = (const float*)d_in[4];
    const float* W_attn  = (const float*)d_in[5];
    const float* W_edge  = (const float*)d_in[6];
    float* out = (float*)d_out;

    gemm_kernel<<<512, 128>>>(ns, W_left, W_right, W_attn);
    attn_kernel<<<N_NODES, 128>>>(edges, ef, W_edge, W_attn, out);
}

// round 15
// speedup vs baseline: 1.9594x; 1.0017x over previous
#include <cuda_runtime.h>
#include <cuda_fp16.h>
#include <cstdint>

#define N_NODES 2048
#define F_DIM   128
#define UNITS   128
#define FE_DIM  16
#define DEG     64

__device__ __half g_hr[N_NODES * UNITS];   // fp16 hr: halves aggregation traffic
__device__ float  g_alp[2][N_NODES];       // al partials per column-half
__device__ float  g_arp[2][N_NODES];       // ar partials per column-half

__device__ __forceinline__ float lrelu(float x) {
    return x > 0.0f ? x : 0.2f * x;
}

__device__ __forceinline__ unsigned long long pack2(float lo, float hi) {
    unsigned long long r;
    asm("mov.b64 %0, {%1, %2};" : "=l"(r) : "f"(lo), "f"(hi));
    return r;
}
__device__ __forceinline__ void unpack2(float& lo, float& hi, unsigned long long v) {
    asm("mov.b64 {%0, %1}, %2;" : "=f"(lo), "=f"(hi) : "l"(v));
}
__device__ __forceinline__ void fma2(unsigned long long& d,
                                     unsigned long long a,
                                     unsigned long long b) {
    asm("fma.rn.f32x2 %0, %1, %2, %3;" : "=l"(d) : "l"(a), "l"(b), "l"(d));
}

// Kernel 1: side+column-split GEMM. 1024 blocks x 128 threads.
//   b = side(1) | colhalf(1) | group(8):  8 nodes, 64 columns per block.
//   thread: col = colbase + (t&63), node-half nh = t>>6 (4 nodes).
// Same W traffic as before (32KB/block), 2x blocks for latency hiding.
#define NPB   8
#define NSPAD 12
__global__ __launch_bounds__(128)
void gemm_kernel(const float* __restrict__ ns,
                 const float* __restrict__ Wl,
                 const float* __restrict__ Wr,
                 const float* __restrict__ W_attn) {
    const int b    = blockIdx.x;
    const int side = b >> 9;                   // 0 = L, 1 = R
    const int ch   = (b >> 8) & 1;             // column half
    const int n0   = (b & 255) * NPB;
    const int t    = threadIdx.x;
    const int col  = ch * 64 + (t & 63);
    const int nh   = t >> 6;                   // node half: nodes nh*4..nh*4+3
    const int w    = t >> 5, lane = t & 31;

    __shared__ float s_ns[F_DIM][NSPAD];       // [k][node 0..7]
    #pragma unroll
    for (int j = 0; j < NPB; j++)
        s_ns[t][j] = ns[(n0 + j) * F_DIM + t];
    __syncthreads();

    const float* __restrict__ W = side ? Wr : Wl;

    unsigned long long acc[2];                 // (n0',n1'), (n2',n3') of this half
    acc[0] = 0ull; acc[1] = 0ull;

    #pragma unroll 8
    for (int k = 0; k < F_DIM; k++) {
        const float wv = W[k * UNITS + col];   // 128B/warp coalesced, L1-cached
        const unsigned long long wp = pack2(wv, wv);
        const ulonglong2 r = *reinterpret_cast<const ulonglong2*>(&s_ns[k][nh * 4]);
        fma2(acc[0], r.x, wp);
        fma2(acc[1], r.y, wp);
    }

    float h[4];
    unpack2(h[0], h[1], acc[0]);
    unpack2(h[2], h[3], acc[1]);

    if (side) {
        #pragma unroll
        for (int j = 0; j < 4; j++)
            g_hr[(n0 + nh * 4 + j) * UNITS + col] = __float2half_rn(h[j]);
    }

    // partial per-node scalar over this block's 64 columns
    const float wa = W_attn[side * UNITS + col];
    __shared__ float s_red[4][4];              // [warp][node-in-half]
    #pragma unroll
    for (int j = 0; j < 4; j++) {
        float p = lrelu(h[j]) * wa;
        #pragma unroll
        for (int o = 16; o > 0; o >>= 1)
            p += __shfl_down_sync(0xffffffffu, p, o);
        if (lane == 0) s_red[w][j] = p;
    }
    __syncthreads();
    if (t < NPB) {
        const int nh2 = t >> 2, j = t & 3;     // node = nh2*4 + j
        const float v = s_red[nh2 * 2][j] + s_red[nh2 * 2 + 1][j];
        float* dstv = side ? g_arp[ch] : g_alp[ch];
        dstv[n0 + nh2 * 4 + j] = v;
    }
}

// Kernel 2: R13/R14 attn (proven 10.8us), al/ar read as two partials.
__global__ __launch_bounds__(128)
void attn_kernel(const int* __restrict__ edges,
                 const float* __restrict__ ef,
                 const float* __restrict__ W_edge,
                 const float* __restrict__ W_attn,
                 float* __restrict__ out) {
    const int n = blockIdx.x;
    const int t = threadIdx.x;
    const int w = t >> 5, lane = t & 31;

    __shared__ float s_wev[FE_DIM];
    __shared__ float s_pd[2][DEG];     // partial dots
    __shared__ float s_score[DEG];
    __shared__ int   s_dst[DEG];
    __shared__ float s_acc[4][UNITS];
    __shared__ float s_part[2];
    __shared__ float s_inv;

    if (t < FE_DIM) {
        float s = 0.0f;
        #pragma unroll
        for (int j = 0; j < FE_DIM; j++)
            s += W_edge[t * FE_DIM + j] * W_attn[2 * UNITS + j];
        s_wev[t] = s;
    }
    if (t < DEG)
        s_dst[t] = reinterpret_cast<const int2*>(edges)[n * DEG + t].y;
    __syncthreads();

    // gather: all 128 threads; thread = (edge er, half hf); 32B per thread.
    {
        const int er = t & 63;
        const int hf = t >> 6;
        const int dst = s_dst[er];
        const float4* p = reinterpret_cast<const float4*>(
            ef + ((size_t)n * N_NODES + (size_t)dst) * FE_DIM) + hf * 2;
        const float4 v0 = p[0];
        const float4 v1 = p[1];
        const float* wv = &s_wev[hf * 8];
        float d = 0.0f;
        d = fmaf(v0.x, wv[0], d);
        d = fmaf(v0.y, wv[1], d);
        d = fmaf(v0.z, wv[2], d);
        d = fmaf(v0.w, wv[3], d);
        d = fmaf(v1.x, wv[4], d);
        d = fmaf(v1.y, wv[5], d);
        d = fmaf(v1.z, wv[6], d);
        d = fmaf(v1.w, wv[7], d);
        s_pd[hf][er] = d;
    }
    __syncthreads();

    // scores + softmax denominator (threads 0..63)
    if (t < DEG) {
        const int dst = s_dst[t];
        const float al = g_alp[0][n]   + g_alp[1][n];
        const float ar = g_arp[0][dst] + g_arp[1][dst];
        float s = al + ar + s_pd[0][t] + s_pd[1][t];
        s = fminf(2.0f, fmaxf(-2.0f, s));
        const float sc = __expf(s);
        s_score[t] = sc;

        float v = sc;
        #pragma unroll
        for (int o = 16; o > 0; o >>= 1)
            v += __shfl_down_sync(0xffffffffu, v, o);
        if (lane == 0) s_part[t >> 5] = v;
    }
    __syncthreads();
    if (t == 0) s_inv = 1.0f / (s_part[0] + s_part[1]);

    // aggregation: warp w -> edges [w*16, +16). Half-warp per edge; lane
    // loads 8 halves (16B LDG.128) of the fp16 hr row; fp32 accumulators.
    const int ebase = w * 16;
    const int sub   = lane >> 4;
    const int c0    = (lane & 15) * 8;

    float acc[8];
    #pragma unroll
    for (int k = 0; k < 8; k++) acc[k] = 0.0f;

    #pragma unroll
    for (int i = 0; i < 8; i++) {
        const int e = ebase + 2 * i + sub;
        const float sc = s_score[e];
        const int4 hv = *reinterpret_cast<const int4*>(
            g_hr + s_dst[e] * UNITS + c0);
        const __half2* hp = reinterpret_cast<const __half2*>(&hv);
        #pragma unroll
        for (int k = 0; k < 4; k++) {
            const float2 f = __half22float2(hp[k]);
            acc[2 * k]     = fmaf(sc, f.x, acc[2 * k]);
            acc[2 * k + 1] = fmaf(sc, f.y, acc[2 * k + 1]);
        }
    }
    #pragma unroll
    for (int k = 0; k < 8; k++)
        acc[k] += __shfl_down_sync(0xffffffffu, acc[k], 16);

    if (lane < 16) {
        *reinterpret_cast<float4*>(&s_acc[w][c0]) =
            make_float4(acc[0], acc[1], acc[2], acc[3]);
        *reinterpret_cast<float4*>(&s_acc[w][c0 + 4]) =
            make_float4(acc[4], acc[5], acc[6], acc[7]);
    }
    __syncthreads();   // also publishes s_inv

    out[n * UNITS + t] =
        (s_acc[0][t] + s_acc[1][t] + s_acc[2][t] + s_acc[3][t]) * s_inv;
}

extern "C" void kernel_launch(void* const* d_in, const int* in_sizes, int n_in,
                              void* d_out, int out_size) {
    const float* ns      = (const float*)d_in[0];
    const int*   edges   = (const int*)d_in[1];
    const float* ef      = (const float*)d_in[2];
    const float* W_left  = (const float*)d_in[3];
    const float* W_right = (const float*)d_in[4];
    const float* W_attn  = (const float*)d_in[5];
    const float* W_edge  = (const float*)d_in[6];
    float* out = (float*)d_out;

    gemm_kernel<<<1024, 128>>>(ns, W_left, W_right, W_attn);
    attn_kernel<<<N_NODES, 128>>>(edges, ef, W_edge, W_attn, out);
}